// round 11
// baseline (speedup 1.0000x reference)
#include <cuda_runtime.h>
#include <math.h>

#define DD 64
#define TWO_PI_F 6.283185307179586f
#define EPS_F 1e-8f

// Device-side scratch (no allocations allowed).
__device__ float g_invA[DD * DD];
__device__ float g_coef;      // used by cold (general) path only
__device__ int g_isdiag;

// ---------------------------------------------------------------------------
// Prep kernel. Fires PDL launch_dependents at ENTRY for maximum overlap.
// Diag fast path: ONLY the off-diagonal check + flag (density computes its
// own av/coef from the Sigma diagonal, pre-wait). General path: Gauss-Jordan
// w/ partial pivoting -> g_invA, g_coef.
// ---------------------------------------------------------------------------
__global__ void prep_kernel(const float* __restrict__ Sigma,
                            const float* __restrict__ Phi) {
    // Let the dependent grid launch NOW — maximum overlap.
    asm volatile("griddepcontrol.launch_dependents;" ::: "memory");

    __shared__ float aug[DD][2 * DD];
    __shared__ float colk[DD];
    __shared__ int s_offdiag;
    __shared__ float s_det;
    __shared__ int s_piv;
    int tid = threadIdx.x;

    if (tid == 0) s_offdiag = 0;
    __syncthreads();

    // One vectorized pass over Sigma: 1024 float4, 256 threads x 4 each.
    {
        const float4* S4 = reinterpret_cast<const float4*>(Sigma);
        float4 c0 = S4[tid * 4 + 0];
        float4 c1 = S4[tid * 4 + 1];
        float4 c2 = S4[tid * 4 + 2];
        float4 c3 = S4[tid * 4 + 3];
        int bad = 0;
        #pragma unroll
        for (int q = 0; q < 4; q++) {
            float4 c = (q == 0) ? c0 : (q == 1) ? c1 : (q == 2) ? c2 : c3;
            int ebase = (tid * 4 + q) * 4;
            float vals[4] = {c.x, c.y, c.z, c.w};
            #pragma unroll
            for (int i = 0; i < 4; i++) {
                int e = ebase + i;
                int r = e >> 6, col = e & 63;
                if (r != col && vals[i] != 0.0f) bad = 1;
            }
        }
        if (bad) atomicOr(&s_offdiag, 1);
    }
    __syncthreads();

    if (!s_offdiag) {
        if (tid == 0) g_isdiag = 1;
        return;  // kernel completion publishes the flag to the waiting grid
    }

    // --- General path: Gauss-Jordan with partial pivoting on [Sigma | I] ---
    for (int i = tid; i < DD * 2 * DD; i += blockDim.x) {
        int r = i / (2 * DD), c = i % (2 * DD);
        aug[r][c] = (c < DD) ? Sigma[r * DD + c]
                             : ((c - DD == r) ? 1.0f : 0.0f);
    }
    if (tid == 0) s_det = 1.0f;
    __syncthreads();

    for (int k = 0; k < DD; k++) {
        if (tid == 0) {
            int p = k;
            float best = fabsf(aug[k][k]);
            for (int r = k + 1; r < DD; r++) {
                float v = fabsf(aug[r][k]);
                if (v > best) { best = v; p = r; }
            }
            s_piv = p;
            if (p != k) s_det = -s_det;
        }
        __syncthreads();
        int p = s_piv;
        if (p != k) {
            for (int c = tid; c < 2 * DD; c += blockDim.x) {
                float t = aug[k][c];
                aug[k][c] = aug[p][c];
                aug[p][c] = t;
            }
            __syncthreads();
        }
        float piv = aug[k][k];
        if (tid == 0) s_det *= piv;
        float inv_piv = (piv != 0.0f) ? 1.0f / piv : 0.0f;
        for (int c = tid; c < 2 * DD; c += blockDim.x) {
            aug[k][c] *= inv_piv;
        }
        if (tid < DD) colk[tid] = (tid == k) ? 0.0f : aug[tid][k];
        __syncthreads();
        for (int i = tid; i < DD * 2 * DD; i += blockDim.x) {
            int r = i / (2 * DD), c = i % (2 * DD);
            if (r != k) aug[r][c] -= colk[r] * aug[k][c];
        }
        __syncthreads();
    }

    for (int i = tid; i < DD * DD; i += blockDim.x) {
        int r = i >> 6, c = i & 63;
        g_invA[i] = aug[r][DD + c];
    }
    if (tid == 0) {
        g_coef = Phi[0] / sqrtf(TWO_PI_F * s_det);
        g_isdiag = 0;
    }
}

// ---------------------------------------------------------------------------
// Main kernel (diag fast path): self-sufficient. Pre-wait it loads its 4
// sample float4s (MLP=4), mu, its 4 Sigma-diagonal entries, Phi, and
// computes av (reciprocals), det (16-lane shfl product: each lane holds the
// product of its own 4 diag entries) and coef — ALL overlapped with prep.
// Post-wait critical path = one g_isdiag load + branch. 32 regs target,
// 8 CTAs/SM; half-warp owns a 4-sample group; STG.128 output.
// ---------------------------------------------------------------------------
__global__ void __launch_bounds__(256, 8)
density_kernel(const float* __restrict__ x,
               const float* __restrict__ Phi,
               const float* __restrict__ mu,
               const float* __restrict__ Sigma,
               float* __restrict__ out, int N) {
    int lane = threadIdx.x & 31;
    int warp_g = (blockIdx.x * blockDim.x + threadIdx.x) >> 5;
    int half = lane >> 4;          // 0 or 1
    int sub = lane & 15;           // 16B chunk within sample
    int base = warp_g * 8 + half * 4;   // first of this thread's 4 samples
    if (base >= N) return;

    // ---- Independent prologue (overlaps prep): sample + param loads ----
    const float4* xr = reinterpret_cast<const float4*>(x);
    float4 xv0 = __ldcs(&xr[(size_t)(base + 0) * 16 + sub]);
    float4 xv1 = __ldcs(&xr[(size_t)(base + 1) * 16 + sub]);
    float4 xv2 = __ldcs(&xr[(size_t)(base + 2) * 16 + sub]);
    float4 xv3 = __ldcs(&xr[(size_t)(base + 3) * 16 + sub]);
    float4 muv = reinterpret_cast<const float4*>(mu)[sub];

    // Sigma diagonal entries owned by this lane: rows sub*4..sub*4+3.
    // 64 unique addresses grid-wide -> L1-resident after first CTA per SM.
    int d0i = sub * 4;
    float s0 = __ldg(&Sigma[(d0i + 0) * DD + (d0i + 0)]);
    float s1 = __ldg(&Sigma[(d0i + 1) * DD + (d0i + 1)]);
    float s2 = __ldg(&Sigma[(d0i + 2) * DD + (d0i + 2)]);
    float s3 = __ldg(&Sigma[(d0i + 3) * DD + (d0i + 3)]);
    float phi = __ldg(&Phi[0]);

    // det over all 64 diag entries: per-lane product of 4, then 16-lane tree.
    float det = s0 * s1 * s2 * s3;
    #pragma unroll
    for (int m = 8; m >= 1; m >>= 1)
        det *= __shfl_xor_sync(0xffffffffu, det, m);
    float coef = phi / sqrtf(TWO_PI_F * det);

    float4 av;   // pinv semantics for the diagonal
    av.x = (s0 != 0.0f) ? 1.0f / s0 : 0.0f;
    av.y = (s1 != 0.0f) ? 1.0f / s1 : 0.0f;
    av.z = (s2 != 0.0f) ? 1.0f / s2 : 0.0f;
    av.w = (s3 != 0.0f) ? 1.0f / s3 : 0.0f;

    // ---- Wait for prep grid completion (publishes g_isdiag / cold data) ----
    asm volatile("griddepcontrol.wait;" ::: "memory");

    if (g_isdiag) {
        float p0, p1, p2, p3;
        {
            float d0 = xv0.x - muv.x, d1 = xv0.y - muv.y,
                  d2 = xv0.z - muv.z, d3 = xv0.w - muv.w;
            p0 = av.x * d0 * d0 + av.y * d1 * d1 + av.z * d2 * d2 + av.w * d3 * d3;
        }
        {
            float d0 = xv1.x - muv.x, d1 = xv1.y - muv.y,
                  d2 = xv1.z - muv.z, d3 = xv1.w - muv.w;
            p1 = av.x * d0 * d0 + av.y * d1 * d1 + av.z * d2 * d2 + av.w * d3 * d3;
        }
        {
            float d0 = xv2.x - muv.x, d1 = xv2.y - muv.y,
                  d2 = xv2.z - muv.z, d3 = xv2.w - muv.w;
            p2 = av.x * d0 * d0 + av.y * d1 * d1 + av.z * d2 * d2 + av.w * d3 * d3;
        }
        {
            float d0 = xv3.x - muv.x, d1 = xv3.y - muv.y,
                  d2 = xv3.z - muv.z, d3 = xv3.w - muv.w;
            p3 = av.x * d0 * d0 + av.y * d1 * d1 + av.z * d2 * d2 + av.w * d3 * d3;
        }

        // 4 independent 16-lane reduction trees.
        #pragma unroll
        for (int m = 8; m >= 1; m >>= 1) {
            p0 += __shfl_xor_sync(0xffffffffu, p0, m);
            p1 += __shfl_xor_sync(0xffffffffu, p1, m);
            p2 += __shfl_xor_sync(0xffffffffu, p2, m);
            p3 += __shfl_xor_sync(0xffffffffu, p3, m);
        }

        if (sub == 0) {
            float4 r;
            r.x = -__logf(coef * __expf(-0.5f * p0) + EPS_F);
            r.y = -__logf(coef * __expf(-0.5f * p1) + EPS_F);
            r.z = -__logf(coef * __expf(-0.5f * p2) + EPS_F);
            r.w = -__logf(coef * __expf(-0.5f * p3) + EPS_F);
            *reinterpret_cast<float4*>(out + base) = r;
        }
    } else {
        // General quadratic form (cold path) — uses prep's g_invA / g_coef.
        if (sub == 0) {
            float gcoef = g_coef;
            for (int j = 0; j < 4; j++) {
                int s = base + j;
                if (s >= N) break;
                const float* xrow = x + (size_t)s * DD;
                float q = 0.0f;
#pragma unroll 1
                for (int e = 0; e < DD; e++) {
                    float de = xrow[e] - mu[e];
                    float t = 0.0f;
#pragma unroll 8
                    for (int d = 0; d < DD; d++)
                        t += g_invA[e * DD + d] * (xrow[d] - mu[d]);
                    q += de * t;
                }
                float dens = gcoef * __expf(-0.5f * q);
                out[s] = -__logf(dens + EPS_F);
            }
        }
    }
}

extern "C" void kernel_launch(void* const* d_in, const int* in_sizes, int n_in,
                              void* d_out, int out_size) {
    const float* samples = (const float*)d_in[0];
    const float* Phi     = (const float*)d_in[1];
    const float* mu      = (const float*)d_in[2];
    const float* Sigma   = (const float*)d_in[3];
    int N = out_size;  // one output per sample

    prep_kernel<<<1, 256>>>(Sigma, Phi);

    // Density launched with PDL; its prologue overlaps prep's execution.
    long long total = (long long)N * 4;   // 4 samples/thread, 16 lanes/sample
    int threads = 256;
    int blocks = (int)((total + threads - 1) / threads);

    cudaLaunchConfig_t cfg = {};
    cfg.gridDim = dim3(blocks, 1, 1);
    cfg.blockDim = dim3(threads, 1, 1);
    cfg.dynamicSmemBytes = 0;
    cfg.stream = 0;
    cudaLaunchAttribute attrs[1];
    attrs[0].id = cudaLaunchAttributeProgrammaticStreamSerialization;
    attrs[0].val.programmaticStreamSerializationAllowed = 1;
    cfg.attrs = attrs;
    cfg.numAttrs = 1;

    cudaLaunchKernelEx(&cfg, density_kernel, samples, Phi, mu, Sigma,
                       (float*)d_out, N);
}

// round 12
// speedup vs baseline: 1.2748x; 1.2748x over previous
#include <cuda_runtime.h>
#include <math.h>

#define DD 64
#define TWO_PI_F 6.283185307179586f
#define EPS_F 1e-8f

// Device-side scratch (no allocations allowed).
__device__ __align__(16) float g_diag[DD];
__device__ float g_invA[DD * DD];
__device__ float g_coef;
__device__ int g_isdiag;

// ---------------------------------------------------------------------------
// Prep kernel. Fires PDL launch_dependents at ENTRY so the density grid
// launches and runs its independent prologue (sample loads) concurrently
// with this kernel's entire execution. density's griddepcontrol.wait gates
// on this kernel's completion, which publishes g_*.
// Diag fast path: vectorized float4 scan (off-diag check + diag gather),
// shfl-product det. General path: Gauss-Jordan w/ partial pivoting.
// ---------------------------------------------------------------------------
__global__ void prep_kernel(const float* __restrict__ Sigma,
                            const float* __restrict__ Phi) {
    // Let the dependent grid launch NOW — maximum overlap.
    asm volatile("griddepcontrol.launch_dependents;" ::: "memory");

    __shared__ float aug[DD][2 * DD];
    __shared__ float colk[DD];
    __shared__ float sdiag[DD];
    __shared__ float s_wprod[2];
    __shared__ int s_offdiag;
    __shared__ float s_det;
    __shared__ int s_piv;
    int tid = threadIdx.x;
    int lane = tid & 31;
    int wid = tid >> 5;

    if (tid == 0) s_offdiag = 0;
    __syncthreads();

    // One vectorized pass over Sigma: 1024 float4, 256 threads x 4 each.
    {
        const float4* S4 = reinterpret_cast<const float4*>(Sigma);
        float4 c0 = S4[tid * 4 + 0];
        float4 c1 = S4[tid * 4 + 1];
        float4 c2 = S4[tid * 4 + 2];
        float4 c3 = S4[tid * 4 + 3];
        int bad = 0;
        #pragma unroll
        for (int q = 0; q < 4; q++) {
            float4 c = (q == 0) ? c0 : (q == 1) ? c1 : (q == 2) ? c2 : c3;
            int ebase = (tid * 4 + q) * 4;
            float vals[4] = {c.x, c.y, c.z, c.w};
            #pragma unroll
            for (int i = 0; i < 4; i++) {
                int e = ebase + i;
                int r = e >> 6, col = e & 63;
                if (r == col) sdiag[r] = vals[i];
                else if (vals[i] != 0.0f) bad = 1;
            }
        }
        if (bad) atomicOr(&s_offdiag, 1);
    }
    __syncthreads();

    if (!s_offdiag) {
        if (tid < DD) {
            float v = sdiag[tid];
            g_diag[tid] = (v != 0.0f) ? 1.0f / v : 0.0f;  // pinv semantics
        }
        if (tid < DD) {
            float v = sdiag[tid];
            #pragma unroll
            for (int m = 16; m >= 1; m >>= 1)
                v *= __shfl_xor_sync(0xffffffffu, v, m);
            if (lane == 0) s_wprod[wid] = v;
        }
        __syncthreads();
        if (tid == 0) {
            float det = s_wprod[0] * s_wprod[1];
            g_coef = Phi[0] / sqrtf(TWO_PI_F * det);
            g_isdiag = 1;
        }
        return;  // kernel completion publishes g_* to the waiting grid
    }

    // --- General path: Gauss-Jordan with partial pivoting on [Sigma | I] ---
    for (int i = tid; i < DD * 2 * DD; i += blockDim.x) {
        int r = i / (2 * DD), c = i % (2 * DD);
        aug[r][c] = (c < DD) ? Sigma[r * DD + c]
                             : ((c - DD == r) ? 1.0f : 0.0f);
    }
    if (tid == 0) s_det = 1.0f;
    __syncthreads();

    for (int k = 0; k < DD; k++) {
        if (tid == 0) {
            int p = k;
            float best = fabsf(aug[k][k]);
            for (int r = k + 1; r < DD; r++) {
                float v = fabsf(aug[r][k]);
                if (v > best) { best = v; p = r; }
            }
            s_piv = p;
            if (p != k) s_det = -s_det;
        }
        __syncthreads();
        int p = s_piv;
        if (p != k) {
            for (int c = tid; c < 2 * DD; c += blockDim.x) {
                float t = aug[k][c];
                aug[k][c] = aug[p][c];
                aug[p][c] = t;
            }
            __syncthreads();
        }
        float piv = aug[k][k];
        if (tid == 0) s_det *= piv;
        float inv_piv = (piv != 0.0f) ? 1.0f / piv : 0.0f;
        for (int c = tid; c < 2 * DD; c += blockDim.x) {
            aug[k][c] *= inv_piv;
        }
        if (tid < DD) colk[tid] = (tid == k) ? 0.0f : aug[tid][k];
        __syncthreads();
        for (int i = tid; i < DD * 2 * DD; i += blockDim.x) {
            int r = i / (2 * DD), c = i % (2 * DD);
            if (r != k) aug[r][c] -= colk[r] * aug[k][c];
        }
        __syncthreads();
    }

    for (int i = tid; i < DD * DD; i += blockDim.x) {
        int r = i >> 6, c = i & 63;
        g_invA[i] = aug[r][DD + c];
    }
    if (tid == 0) {
        g_coef = Phi[0] / sqrtf(TWO_PI_F * s_det);
        g_isdiag = 0;
    }
}

// ---------------------------------------------------------------------------
// Main kernel (diag fast path): R10-proven config. 4 samples per thread,
// 4 front-batched __ldcs LDG.128 (MLP_p1=4) issued BEFORE the PDL wait so
// they overlap prep's execution; 32 regs, 8 CTAs/SM. Post-wait, all three
// g_* loads (isdiag, diag vector, coef) are issued back-to-back so their
// latencies overlap instead of serializing through the branch.
// ---------------------------------------------------------------------------
__global__ void __launch_bounds__(256, 8)
density_kernel(const float* __restrict__ x,
               const float* __restrict__ mu,
               float* __restrict__ out, int N) {
    int lane = threadIdx.x & 31;
    int warp_g = (blockIdx.x * blockDim.x + threadIdx.x) >> 5;
    int half = lane >> 4;          // 0 or 1
    int sub = lane & 15;           // 16B chunk within sample
    int base = warp_g * 8 + half * 4;   // first of this thread's 4 samples
    if (base >= N) return;

    // ---- Independent prologue: loads of x and mu don't depend on prep ----
    const float4* xr = reinterpret_cast<const float4*>(x);
    float4 xv0 = __ldcs(&xr[(size_t)(base + 0) * 16 + sub]);
    float4 xv1 = __ldcs(&xr[(size_t)(base + 1) * 16 + sub]);
    float4 xv2 = __ldcs(&xr[(size_t)(base + 2) * 16 + sub]);
    float4 xv3 = __ldcs(&xr[(size_t)(base + 3) * 16 + sub]);
    float4 muv = reinterpret_cast<const float4*>(mu)[sub];

    // ---- Wait for prep grid completion (publishes g_*) ----
    asm volatile("griddepcontrol.wait;" ::: "memory");

    // Issue all prep-result loads together (overlapped latencies).
    int isdiag = *(volatile int*)&g_isdiag;
    float4 av = reinterpret_cast<const float4*>(g_diag)[sub];
    float coef = g_coef;

    if (isdiag) {
        float p0, p1, p2, p3;
        {
            float d0 = xv0.x - muv.x, d1 = xv0.y - muv.y,
                  d2 = xv0.z - muv.z, d3 = xv0.w - muv.w;
            p0 = av.x * d0 * d0 + av.y * d1 * d1 + av.z * d2 * d2 + av.w * d3 * d3;
        }
        {
            float d0 = xv1.x - muv.x, d1 = xv1.y - muv.y,
                  d2 = xv1.z - muv.z, d3 = xv1.w - muv.w;
            p1 = av.x * d0 * d0 + av.y * d1 * d1 + av.z * d2 * d2 + av.w * d3 * d3;
        }
        {
            float d0 = xv2.x - muv.x, d1 = xv2.y - muv.y,
                  d2 = xv2.z - muv.z, d3 = xv2.w - muv.w;
            p2 = av.x * d0 * d0 + av.y * d1 * d1 + av.z * d2 * d2 + av.w * d3 * d3;
        }
        {
            float d0 = xv3.x - muv.x, d1 = xv3.y - muv.y,
                  d2 = xv3.z - muv.z, d3 = xv3.w - muv.w;
            p3 = av.x * d0 * d0 + av.y * d1 * d1 + av.z * d2 * d2 + av.w * d3 * d3;
        }

        // 4 independent 16-lane reduction trees (masks < 16 keep halves
        // separate).
        #pragma unroll
        for (int m = 8; m >= 1; m >>= 1) {
            p0 += __shfl_xor_sync(0xffffffffu, p0, m);
            p1 += __shfl_xor_sync(0xffffffffu, p1, m);
            p2 += __shfl_xor_sync(0xffffffffu, p2, m);
            p3 += __shfl_xor_sync(0xffffffffu, p3, m);
        }

        if (sub == 0) {
            float4 r;
            r.x = -__logf(coef * __expf(-0.5f * p0) + EPS_F);
            r.y = -__logf(coef * __expf(-0.5f * p1) + EPS_F);
            r.z = -__logf(coef * __expf(-0.5f * p2) + EPS_F);
            r.w = -__logf(coef * __expf(-0.5f * p3) + EPS_F);
            *reinterpret_cast<float4*>(out + base) = r;
        }
    } else {
        // General quadratic form (cold path).
        if (sub == 0) {
            for (int j = 0; j < 4; j++) {
                int s = base + j;
                if (s >= N) break;
                const float* xrow = x + (size_t)s * DD;
                float q = 0.0f;
#pragma unroll 1
                for (int e = 0; e < DD; e++) {
                    float de = xrow[e] - mu[e];
                    float t = 0.0f;
#pragma unroll 8
                    for (int d = 0; d < DD; d++)
                        t += g_invA[e * DD + d] * (xrow[d] - mu[d]);
                    q += de * t;
                }
                float dens = coef * __expf(-0.5f * q);
                out[s] = -__logf(dens + EPS_F);
            }
        }
    }
}

extern "C" void kernel_launch(void* const* d_in, const int* in_sizes, int n_in,
                              void* d_out, int out_size) {
    const float* samples = (const float*)d_in[0];
    const float* Phi     = (const float*)d_in[1];
    const float* mu      = (const float*)d_in[2];
    const float* Sigma   = (const float*)d_in[3];
    int N = out_size;  // one output per sample

    prep_kernel<<<1, 256>>>(Sigma, Phi);

    // Density launched with PDL; its prologue overlaps prep's execution.
    long long total = (long long)N * 4;   // 4 samples/thread, 16 lanes/sample
    int threads = 256;
    int blocks = (int)((total + threads - 1) / threads);

    cudaLaunchConfig_t cfg = {};
    cfg.gridDim = dim3(blocks, 1, 1);
    cfg.blockDim = dim3(threads, 1, 1);
    cfg.dynamicSmemBytes = 0;
    cfg.stream = 0;
    cudaLaunchAttribute attrs[1];
    attrs[0].id = cudaLaunchAttributeProgrammaticStreamSerialization;
    attrs[0].val.programmaticStreamSerializationAllowed = 1;
    cfg.attrs = attrs;
    cfg.numAttrs = 1;

    cudaLaunchKernelEx(&cfg, density_kernel, samples, mu, (float*)d_out, N);
}

// round 13
// speedup vs baseline: 1.2795x; 1.0037x over previous
#include <cuda_runtime.h>
#include <math.h>

#define DD 64
#define TWO_PI_F 6.283185307179586f
#define EPS_F 1e-8f

// Device-side scratch (no allocations allowed).
__device__ __align__(16) float g_diag[DD];
__device__ float g_invA[DD * DD];
__device__ float g_coef;
__device__ int g_isdiag;

// ---------------------------------------------------------------------------
// Prep kernel. Fires PDL launch_dependents at ENTRY so the density grid
// launches and runs its independent prologue (sample loads) concurrently
// with this kernel's entire execution. density's griddepcontrol.wait gates
// on this kernel's completion (+ implicit memory visibility), so g_* are
// safely published regardless of trigger position.
// Diag fast path: vectorized float4 scan (off-diag check + diag gather),
// shfl-product det. General path: Gauss-Jordan w/ partial pivoting.
// ---------------------------------------------------------------------------
__global__ void prep_kernel(const float* __restrict__ Sigma,
                            const float* __restrict__ Phi) {
    // Let the dependent grid launch NOW — maximum overlap.
    asm volatile("griddepcontrol.launch_dependents;" ::: "memory");

    __shared__ float aug[DD][2 * DD];
    __shared__ float colk[DD];
    __shared__ float sdiag[DD];
    __shared__ float s_wprod[2];
    __shared__ int s_offdiag;
    __shared__ float s_det;
    __shared__ int s_piv;
    int tid = threadIdx.x;
    int lane = tid & 31;
    int wid = tid >> 5;

    if (tid == 0) s_offdiag = 0;
    __syncthreads();

    // One vectorized pass over Sigma: 1024 float4, 256 threads x 4 each.
    {
        const float4* S4 = reinterpret_cast<const float4*>(Sigma);
        float4 c0 = S4[tid * 4 + 0];
        float4 c1 = S4[tid * 4 + 1];
        float4 c2 = S4[tid * 4 + 2];
        float4 c3 = S4[tid * 4 + 3];
        int bad = 0;
        #pragma unroll
        for (int q = 0; q < 4; q++) {
            float4 c = (q == 0) ? c0 : (q == 1) ? c1 : (q == 2) ? c2 : c3;
            int ebase = (tid * 4 + q) * 4;
            float vals[4] = {c.x, c.y, c.z, c.w};
            #pragma unroll
            for (int i = 0; i < 4; i++) {
                int e = ebase + i;
                int r = e >> 6, col = e & 63;
                if (r == col) sdiag[r] = vals[i];
                else if (vals[i] != 0.0f) bad = 1;
            }
        }
        if (bad) atomicOr(&s_offdiag, 1);
    }
    __syncthreads();

    if (!s_offdiag) {
        if (tid < DD) {
            float v = sdiag[tid];
            g_diag[tid] = (v != 0.0f) ? 1.0f / v : 0.0f;  // pinv semantics
        }
        if (tid < DD) {
            float v = sdiag[tid];
            #pragma unroll
            for (int m = 16; m >= 1; m >>= 1)
                v *= __shfl_xor_sync(0xffffffffu, v, m);
            if (lane == 0) s_wprod[wid] = v;
        }
        __syncthreads();
        if (tid == 0) {
            float det = s_wprod[0] * s_wprod[1];
            g_coef = Phi[0] / sqrtf(TWO_PI_F * det);
            g_isdiag = 1;
        }
        return;  // kernel completion publishes g_* to the waiting grid
    }

    // --- General path: Gauss-Jordan with partial pivoting on [Sigma | I] ---
    for (int i = tid; i < DD * 2 * DD; i += blockDim.x) {
        int r = i / (2 * DD), c = i % (2 * DD);
        aug[r][c] = (c < DD) ? Sigma[r * DD + c]
                             : ((c - DD == r) ? 1.0f : 0.0f);
    }
    if (tid == 0) s_det = 1.0f;
    __syncthreads();

    for (int k = 0; k < DD; k++) {
        if (tid == 0) {
            int p = k;
            float best = fabsf(aug[k][k]);
            for (int r = k + 1; r < DD; r++) {
                float v = fabsf(aug[r][k]);
                if (v > best) { best = v; p = r; }
            }
            s_piv = p;
            if (p != k) s_det = -s_det;
        }
        __syncthreads();
        int p = s_piv;
        if (p != k) {
            for (int c = tid; c < 2 * DD; c += blockDim.x) {
                float t = aug[k][c];
                aug[k][c] = aug[p][c];
                aug[p][c] = t;
            }
            __syncthreads();
        }
        float piv = aug[k][k];
        if (tid == 0) s_det *= piv;
        float inv_piv = (piv != 0.0f) ? 1.0f / piv : 0.0f;
        for (int c = tid; c < 2 * DD; c += blockDim.x) {
            aug[k][c] *= inv_piv;
        }
        if (tid < DD) colk[tid] = (tid == k) ? 0.0f : aug[tid][k];
        __syncthreads();
        for (int i = tid; i < DD * 2 * DD; i += blockDim.x) {
            int r = i / (2 * DD), c = i % (2 * DD);
            if (r != k) aug[r][c] -= colk[r] * aug[k][c];
        }
        __syncthreads();
    }

    for (int i = tid; i < DD * DD; i += blockDim.x) {
        int r = i >> 6, c = i & 63;
        g_invA[i] = aug[r][DD + c];
    }
    if (tid == 0) {
        g_coef = Phi[0] / sqrtf(TWO_PI_F * s_det);
        g_isdiag = 0;
    }
}

// ---------------------------------------------------------------------------
// Main kernel (diag fast path): proven config. 4 samples per thread,
// 4 front-batched __ldcs LDG.128 (MLP_p1=4) issued BEFORE the PDL wait so
// they overlap prep's execution; 32 regs, 8 CTAs/SM. Half-warp owns a
// 4-sample group; 4 shfl trees; lane sub==0 writes one STG.128. All g_*
// reads use the normal cached path (L1-resident after first touch per SM).
// ---------------------------------------------------------------------------
__global__ void __launch_bounds__(256, 8)
density_kernel(const float* __restrict__ x,
               const float* __restrict__ mu,
               float* __restrict__ out, int N) {
    int lane = threadIdx.x & 31;
    int warp_g = (blockIdx.x * blockDim.x + threadIdx.x) >> 5;
    int half = lane >> 4;          // 0 or 1
    int sub = lane & 15;           // 16B chunk within sample
    int base = warp_g * 8 + half * 4;   // first of this thread's 4 samples
    if (base >= N) return;

    // ---- Independent prologue: loads of x and mu don't depend on prep ----
    const float4* xr = reinterpret_cast<const float4*>(x);
    float4 xv0 = __ldcs(&xr[(size_t)(base + 0) * 16 + sub]);
    float4 xv1 = __ldcs(&xr[(size_t)(base + 1) * 16 + sub]);
    float4 xv2 = __ldcs(&xr[(size_t)(base + 2) * 16 + sub]);
    float4 xv3 = __ldcs(&xr[(size_t)(base + 3) * 16 + sub]);
    float4 muv = reinterpret_cast<const float4*>(mu)[sub];

    // ---- Wait for prep grid completion (publishes g_*) ----
    asm volatile("griddepcontrol.wait;" ::: "memory");

    if (g_isdiag) {
        float4 av = reinterpret_cast<const float4*>(g_diag)[sub];

        float p0, p1, p2, p3;
        {
            float d0 = xv0.x - muv.x, d1 = xv0.y - muv.y,
                  d2 = xv0.z - muv.z, d3 = xv0.w - muv.w;
            p0 = av.x * d0 * d0 + av.y * d1 * d1 + av.z * d2 * d2 + av.w * d3 * d3;
        }
        {
            float d0 = xv1.x - muv.x, d1 = xv1.y - muv.y,
                  d2 = xv1.z - muv.z, d3 = xv1.w - muv.w;
            p1 = av.x * d0 * d0 + av.y * d1 * d1 + av.z * d2 * d2 + av.w * d3 * d3;
        }
        {
            float d0 = xv2.x - muv.x, d1 = xv2.y - muv.y,
                  d2 = xv2.z - muv.z, d3 = xv2.w - muv.w;
            p2 = av.x * d0 * d0 + av.y * d1 * d1 + av.z * d2 * d2 + av.w * d3 * d3;
        }
        {
            float d0 = xv3.x - muv.x, d1 = xv3.y - muv.y,
                  d2 = xv3.z - muv.z, d3 = xv3.w - muv.w;
            p3 = av.x * d0 * d0 + av.y * d1 * d1 + av.z * d2 * d2 + av.w * d3 * d3;
        }

        // 4 independent 16-lane reduction trees (masks < 16 keep halves
        // separate).
        #pragma unroll
        for (int m = 8; m >= 1; m >>= 1) {
            p0 += __shfl_xor_sync(0xffffffffu, p0, m);
            p1 += __shfl_xor_sync(0xffffffffu, p1, m);
            p2 += __shfl_xor_sync(0xffffffffu, p2, m);
            p3 += __shfl_xor_sync(0xffffffffu, p3, m);
        }

        if (sub == 0) {
            float coef = g_coef;
            float4 r;
            r.x = -__logf(coef * __expf(-0.5f * p0) + EPS_F);
            r.y = -__logf(coef * __expf(-0.5f * p1) + EPS_F);
            r.z = -__logf(coef * __expf(-0.5f * p2) + EPS_F);
            r.w = -__logf(coef * __expf(-0.5f * p3) + EPS_F);
            *reinterpret_cast<float4*>(out + base) = r;
        }
    } else {
        // General quadratic form (cold path).
        if (sub == 0) {
            for (int j = 0; j < 4; j++) {
                int s = base + j;
                if (s >= N) break;
                const float* xrow = x + (size_t)s * DD;
                float q = 0.0f;
#pragma unroll 1
                for (int e = 0; e < DD; e++) {
                    float de = xrow[e] - mu[e];
                    float t = 0.0f;
#pragma unroll 8
                    for (int d = 0; d < DD; d++)
                        t += g_invA[e * DD + d] * (xrow[d] - mu[d]);
                    q += de * t;
                }
                float dens = g_coef * __expf(-0.5f * q);
                out[s] = -__logf(dens + EPS_F);
            }
        }
    }
}

extern "C" void kernel_launch(void* const* d_in, const int* in_sizes, int n_in,
                              void* d_out, int out_size) {
    const float* samples = (const float*)d_in[0];
    const float* Phi     = (const float*)d_in[1];
    const float* mu      = (const float*)d_in[2];
    const float* Sigma   = (const float*)d_in[3];
    int N = out_size;  // one output per sample

    prep_kernel<<<1, 256>>>(Sigma, Phi);

    // Density launched with PDL; its prologue overlaps prep's execution.
    long long total = (long long)N * 4;   // 4 samples/thread, 16 lanes/sample
    int threads = 256;
    int blocks = (int)((total + threads - 1) / threads);

    cudaLaunchConfig_t cfg = {};
    cfg.gridDim = dim3(blocks, 1, 1);
    cfg.blockDim = dim3(threads, 1, 1);
    cfg.dynamicSmemBytes = 0;
    cfg.stream = 0;
    cudaLaunchAttribute attrs[1];
    attrs[0].id = cudaLaunchAttributeProgrammaticStreamSerialization;
    attrs[0].val.programmaticStreamSerializationAllowed = 1;
    cfg.attrs = attrs;
    cfg.numAttrs = 1;

    cudaLaunchKernelEx(&cfg, density_kernel, samples, mu, (float*)d_out, N);
}

// round 14
// speedup vs baseline: 1.4540x; 1.1363x over previous
#include <cuda_runtime.h>
#include <math.h>

#define DD 64
#define TWO_PI_F 6.283185307179586f
#define EPS_F 1e-8f

// Device-side scratch (no allocations allowed).
__device__ __align__(16) float g_diag[DD];
__device__ float g_invA[DD * DD];
__device__ float g_coef;
__device__ int g_isdiag;

// ---------------------------------------------------------------------------
// Prep kernel (512 threads — shortest possible serial shadow). Fires PDL
// launch_dependents at ENTRY so the density grid launches and overlaps its
// prologue with this kernel. Diag fast path: vectorized float4 scan
// (off-diag check + diag gather), shfl-product det. General path:
// Gauss-Jordan w/ partial pivoting.
// ---------------------------------------------------------------------------
__global__ void prep_kernel(const float* __restrict__ Sigma,
                            const float* __restrict__ Phi) {
    // Let the dependent grid launch NOW — maximum overlap.
    asm volatile("griddepcontrol.launch_dependents;" ::: "memory");

    __shared__ float aug[DD][2 * DD];
    __shared__ float colk[DD];
    __shared__ float sdiag[DD];
    __shared__ float s_wprod[2];
    __shared__ int s_offdiag;
    __shared__ float s_det;
    __shared__ int s_piv;
    int tid = threadIdx.x;
    int lane = tid & 31;
    int wid = tid >> 5;

    if (tid == 0) s_offdiag = 0;
    __syncthreads();

    // One vectorized pass over Sigma: 1024 float4, 512 threads x 2 each.
    {
        const float4* S4 = reinterpret_cast<const float4*>(Sigma);
        float4 c0 = S4[tid * 2 + 0];
        float4 c1 = S4[tid * 2 + 1];
        int bad = 0;
        #pragma unroll
        for (int q = 0; q < 2; q++) {
            float4 c = (q == 0) ? c0 : c1;
            int ebase = (tid * 2 + q) * 4;
            float vals[4] = {c.x, c.y, c.z, c.w};
            #pragma unroll
            for (int i = 0; i < 4; i++) {
                int e = ebase + i;
                int r = e >> 6, col = e & 63;
                if (r == col) sdiag[r] = vals[i];
                else if (vals[i] != 0.0f) bad = 1;
            }
        }
        if (bad) atomicOr(&s_offdiag, 1);
    }
    __syncthreads();

    if (!s_offdiag) {
        if (tid < DD) {
            float v = sdiag[tid];
            g_diag[tid] = (v != 0.0f) ? 1.0f / v : 0.0f;  // pinv semantics
        }
        if (tid < DD) {
            float v = sdiag[tid];
            #pragma unroll
            for (int m = 16; m >= 1; m >>= 1)
                v *= __shfl_xor_sync(0xffffffffu, v, m);
            if (lane == 0) s_wprod[wid] = v;
        }
        __syncthreads();
        if (tid == 0) {
            float det = s_wprod[0] * s_wprod[1];
            g_coef = Phi[0] / sqrtf(TWO_PI_F * det);
            g_isdiag = 1;
        }
        return;  // kernel completion publishes g_* to the waiting grid
    }

    // --- General path: Gauss-Jordan with partial pivoting on [Sigma | I] ---
    for (int i = tid; i < DD * 2 * DD; i += blockDim.x) {
        int r = i / (2 * DD), c = i % (2 * DD);
        aug[r][c] = (c < DD) ? Sigma[r * DD + c]
                             : ((c - DD == r) ? 1.0f : 0.0f);
    }
    if (tid == 0) s_det = 1.0f;
    __syncthreads();

    for (int k = 0; k < DD; k++) {
        if (tid == 0) {
            int p = k;
            float best = fabsf(aug[k][k]);
            for (int r = k + 1; r < DD; r++) {
                float v = fabsf(aug[r][k]);
                if (v > best) { best = v; p = r; }
            }
            s_piv = p;
            if (p != k) s_det = -s_det;
        }
        __syncthreads();
        int p = s_piv;
        if (p != k) {
            for (int c = tid; c < 2 * DD; c += blockDim.x) {
                float t = aug[k][c];
                aug[k][c] = aug[p][c];
                aug[p][c] = t;
            }
            __syncthreads();
        }
        float piv = aug[k][k];
        if (tid == 0) s_det *= piv;
        float inv_piv = (piv != 0.0f) ? 1.0f / piv : 0.0f;
        for (int c = tid; c < 2 * DD; c += blockDim.x) {
            aug[k][c] *= inv_piv;
        }
        if (tid < DD) colk[tid] = (tid == k) ? 0.0f : aug[tid][k];
        __syncthreads();
        for (int i = tid; i < DD * 2 * DD; i += blockDim.x) {
            int r = i / (2 * DD), c = i % (2 * DD);
            if (r != k) aug[r][c] -= colk[r] * aug[k][c];
        }
        __syncthreads();
    }

    for (int i = tid; i < DD * DD; i += blockDim.x) {
        int r = i >> 6, c = i & 63;
        g_invA[i] = aug[r][DD + c];
    }
    if (tid == 0) {
        g_coef = Phi[0] / sqrtf(TWO_PI_F * s_det);
        g_isdiag = 0;
    }
}

// ---------------------------------------------------------------------------
// Main kernel (diag fast path): R3-measured-best body (plain LDG, no ldcs —
// DRAM 80.1% vs 78-79% with ldcs). 4 samples per thread, 4 front-batched
// LDG.128 (MLP_p1=4) issued BEFORE the PDL wait; 32 regs, 8 CTAs/SM.
// Half-warp owns a 4-sample group; 4 shfl trees; lane sub==0 writes one
// STG.128.
// ---------------------------------------------------------------------------
__global__ void __launch_bounds__(256, 8)
density_kernel(const float* __restrict__ x,
               const float* __restrict__ mu,
               float* __restrict__ out, int N) {
    int lane = threadIdx.x & 31;
    int warp_g = (blockIdx.x * blockDim.x + threadIdx.x) >> 5;
    int half = lane >> 4;          // 0 or 1
    int sub = lane & 15;           // 16B chunk within sample
    int base = warp_g * 8 + half * 4;   // first of this thread's 4 samples
    if (base >= N) return;

    // ---- Independent prologue: loads of x and mu don't depend on prep ----
    const float4* xr = reinterpret_cast<const float4*>(x);
    float4 xv0 = xr[(size_t)(base + 0) * 16 + sub];
    float4 xv1 = xr[(size_t)(base + 1) * 16 + sub];
    float4 xv2 = xr[(size_t)(base + 2) * 16 + sub];
    float4 xv3 = xr[(size_t)(base + 3) * 16 + sub];
    float4 muv = reinterpret_cast<const float4*>(mu)[sub];

    // ---- Wait for prep grid completion (publishes g_*) ----
    asm volatile("griddepcontrol.wait;" ::: "memory");

    if (g_isdiag) {
        float4 av = reinterpret_cast<const float4*>(g_diag)[sub];

        float p0, p1, p2, p3;
        {
            float d0 = xv0.x - muv.x, d1 = xv0.y - muv.y,
                  d2 = xv0.z - muv.z, d3 = xv0.w - muv.w;
            p0 = av.x * d0 * d0 + av.y * d1 * d1 + av.z * d2 * d2 + av.w * d3 * d3;
        }
        {
            float d0 = xv1.x - muv.x, d1 = xv1.y - muv.y,
                  d2 = xv1.z - muv.z, d3 = xv1.w - muv.w;
            p1 = av.x * d0 * d0 + av.y * d1 * d1 + av.z * d2 * d2 + av.w * d3 * d3;
        }
        {
            float d0 = xv2.x - muv.x, d1 = xv2.y - muv.y,
                  d2 = xv2.z - muv.z, d3 = xv2.w - muv.w;
            p2 = av.x * d0 * d0 + av.y * d1 * d1 + av.z * d2 * d2 + av.w * d3 * d3;
        }
        {
            float d0 = xv3.x - muv.x, d1 = xv3.y - muv.y,
                  d2 = xv3.z - muv.z, d3 = xv3.w - muv.w;
            p3 = av.x * d0 * d0 + av.y * d1 * d1 + av.z * d2 * d2 + av.w * d3 * d3;
        }

        // 4 independent 16-lane reduction trees (masks < 16 keep halves
        // separate).
        #pragma unroll
        for (int m = 8; m >= 1; m >>= 1) {
            p0 += __shfl_xor_sync(0xffffffffu, p0, m);
            p1 += __shfl_xor_sync(0xffffffffu, p1, m);
            p2 += __shfl_xor_sync(0xffffffffu, p2, m);
            p3 += __shfl_xor_sync(0xffffffffu, p3, m);
        }

        if (sub == 0) {
            float coef = g_coef;
            float4 r;
            r.x = -__logf(coef * __expf(-0.5f * p0) + EPS_F);
            r.y = -__logf(coef * __expf(-0.5f * p1) + EPS_F);
            r.z = -__logf(coef * __expf(-0.5f * p2) + EPS_F);
            r.w = -__logf(coef * __expf(-0.5f * p3) + EPS_F);
            *reinterpret_cast<float4*>(out + base) = r;
        }
    } else {
        // General quadratic form (cold path).
        if (sub == 0) {
            for (int j = 0; j < 4; j++) {
                int s = base + j;
                if (s >= N) break;
                const float* xrow = x + (size_t)s * DD;
                float q = 0.0f;
#pragma unroll 1
                for (int e = 0; e < DD; e++) {
                    float de = xrow[e] - mu[e];
                    float t = 0.0f;
#pragma unroll 8
                    for (int d = 0; d < DD; d++)
                        t += g_invA[e * DD + d] * (xrow[d] - mu[d]);
                    q += de * t;
                }
                float dens = g_coef * __expf(-0.5f * q);
                out[s] = -__logf(dens + EPS_F);
            }
        }
    }
}

extern "C" void kernel_launch(void* const* d_in, const int* in_sizes, int n_in,
                              void* d_out, int out_size) {
    const float* samples = (const float*)d_in[0];
    const float* Phi     = (const float*)d_in[1];
    const float* mu      = (const float*)d_in[2];
    const float* Sigma   = (const float*)d_in[3];
    int N = out_size;  // one output per sample

    prep_kernel<<<1, 512>>>(Sigma, Phi);

    // Density launched with PDL; its prologue overlaps prep's execution.
    long long total = (long long)N * 4;   // 4 samples/thread, 16 lanes/sample
    int threads = 256;
    int blocks = (int)((total + threads - 1) / threads);

    cudaLaunchConfig_t cfg = {};
    cfg.gridDim = dim3(blocks, 1, 1);
    cfg.blockDim = dim3(threads, 1, 1);
    cfg.dynamicSmemBytes = 0;
    cfg.stream = 0;
    cudaLaunchAttribute attrs[1];
    attrs[0].id = cudaLaunchAttributeProgrammaticStreamSerialization;
    attrs[0].val.programmaticStreamSerializationAllowed = 1;
    cfg.attrs = attrs;
    cfg.numAttrs = 1;

    cudaLaunchKernelEx(&cfg, density_kernel, samples, mu, (float*)d_out, N);
}